// round 11
// baseline (speedup 1.0000x reference)
#include <cuda_runtime.h>
#include <cuda_bf16.h>
#include <stdint.h>

// GRU reset-on-terminate, T=8192, H=1024. Segment-parallel; mma.sync bf16
// with fp32 hi/lo split (3 terms). R11: 64x64 warp tiles (smem off the
// critical path), block 128x256, 1 CTA x 256 thr per SM (256-reg budget).

#define TS   8192
#define HD   1024
#define N3H  3072
#define NTH  256
#define GRID 148

#define APITCH 80
#define BPITCH 528
#define SA_PL  (128*APITCH)            // 10240
#define SB_PL  (32*BPITCH)             // 16896
#define BUFSZ  (2*SA_PL + 2*SB_PL)     // 54272
#define SMEM_DYN (2*BUFSZ)             // 108544

#define PARTROWS 1536
#define PARTF  ((size_t)PARTROWS*N3H)

__device__ float g_gi[(size_t)TS*N3H];
__device__ float g_gh[(size_t)TS*N3H];
__device__ float g_ghp[(size_t)16*PARTF];
__device__ __nv_bfloat16 g_whi[(size_t)2*HD*N3H];
__device__ __nv_bfloat16 g_wlo[(size_t)2*HD*N3H];
__device__ __nv_bfloat16 g_xhi[(size_t)TS*HD];
__device__ __nv_bfloat16 g_xlo[(size_t)TS*HD];
__device__ __nv_bfloat16 g_hhi[(size_t)TS*HD];
__device__ __nv_bfloat16 g_hlo[(size_t)TS*HD];
__device__ int g_perm[TS], g_cnt[TS], g_off[TS+1], g_l[TS];
__device__ int g_maxL;
__device__ unsigned long long g_bar;

__shared__ int s_perm[128];

// ---------------- helpers ----------------
__device__ __forceinline__ uint32_t smem_u32(const void* p) {
    uint32_t a;
    asm("{ .reg .u64 t; cvta.to.shared.u64 t, %1; cvt.u32.u64 %0, t; }" : "=r"(a) : "l"(p));
    return a;
}
__device__ __forceinline__ void cp16(uint32_t dst, const void* src, bool pred) {
    int sz = pred ? 16 : 0;
    asm volatile("cp.async.cg.shared.global [%0], [%1], 16, %2;"
                 :: "r"(dst), "l"(src), "r"(sz) : "memory");
}
__device__ __forceinline__ void cp_commit() {
    asm volatile("cp.async.commit_group;" ::: "memory");
}
__device__ __forceinline__ void cp_wait1() {
    asm volatile("cp.async.wait_group 1;" ::: "memory");
}
__device__ __forceinline__ void cp_wait0() {
    asm volatile("cp.async.wait_group 0;" ::: "memory");
}
__device__ __forceinline__ void ldm_x4(uint32_t* r, uint32_t a) {
    asm volatile("ldmatrix.sync.aligned.m8n8.x4.shared.b16 {%0,%1,%2,%3}, [%4];"
        : "=r"(r[0]), "=r"(r[1]), "=r"(r[2]), "=r"(r[3]) : "r"(a));
}
__device__ __forceinline__ void ldm_x4t(uint32_t* r, uint32_t a) {
    asm volatile("ldmatrix.sync.aligned.m8n8.x4.trans.shared.b16 {%0,%1,%2,%3}, [%4];"
        : "=r"(r[0]), "=r"(r[1]), "=r"(r[2]), "=r"(r[3]) : "r"(a));
}
__device__ __forceinline__ void mma16816(float* c, const uint32_t* a, const uint32_t* b) {
    asm volatile("mma.sync.aligned.m16n8k16.row.col.f32.bf16.bf16.f32 "
        "{%0,%1,%2,%3}, {%4,%5,%6,%7}, {%8,%9}, {%0,%1,%2,%3};"
        : "+f"(c[0]), "+f"(c[1]), "+f"(c[2]), "+f"(c[3])
        : "r"(a[0]), "r"(a[1]), "r"(a[2]), "r"(a[3]), "r"(b[0]), "r"(b[1]));
}
__device__ __forceinline__ void grid_sync() {
    __threadfence();
    __syncthreads();
    if (threadIdx.x == 0) {
        unsigned long long my = atomicAdd(&g_bar, 1ULL) + 1ULL;
        unsigned long long target = ((my + GRID - 1ULL) / GRID) * GRID;
        while (atomicAdd(&g_bar, 0ULL) < target) { __nanosleep(128); }
        __threadfence();
    }
    __syncthreads();
}
__device__ __forceinline__ int pick_ks(int mtn) {
    return mtn >= 13 ? 1 : (mtn >= 7 ? 2 : (mtn >= 4 ? 4 : (mtn >= 2 ? 8 : 16)));
}

// ---------------- bucketize (block 0, 256 thr x 32) ----------------
__device__ void bucketize(const int* __restrict__ term) {
    __shared__ int s_cm[NTH], s_ml[NTH];
    const int tid = threadIdx.x;
    for (int i = tid; i < TS; i += NTH) g_cnt[i] = 0;
    __syncthreads();
    const int t0 = tid * 32;
    int cm = -1;
#pragma unroll
    for (int i = 0; i < 32; i++) if (term[t0 + i] != 0) cm = t0 + i;
    s_cm[tid] = cm;
    __syncthreads();
    int pre = -1;
    for (int c = 0; c < tid; c++) pre = max(pre, s_cm[c]);
    int run = pre, ml = 0;
    for (int i = 0; i < 32; i++) {
        int t = t0 + i;
        if (term[t] != 0) run = t;
        int l = (run < 0) ? t : (t - run);
        g_l[t] = l;
        atomicAdd(&g_cnt[l], 1);
        ml = max(ml, l);
    }
    s_ml[tid] = ml;
    __syncthreads();
    if (tid == 0) {
        int m = 0;
        for (int c = 0; c < NTH; c++) m = max(m, s_ml[c]);
        g_maxL = m;
        int o = 0;
        for (int s = 0; s <= m; s++) { g_off[s] = o; o += g_cnt[s]; }
        g_off[m + 1] = o;
        for (int s = 0; s <= m; s++) g_cnt[s] = 0;
    }
    __syncthreads();
    for (int i = 0; i < 32; i++) {
        int t = t0 + i;
        int l = g_l[t];
        int pos = g_off[l] + atomicAdd(&g_cnt[l], 1);
        g_perm[pos] = t;
    }
}

// ---------------- split precompute ----------------
__device__ __forceinline__ void split4(float4 v, __nv_bfloat16* hi, __nv_bfloat16* lo) {
    float f[4] = {v.x, v.y, v.z, v.w};
#pragma unroll
    for (int q = 0; q < 4; q++) {
        __nv_bfloat16 h = __float2bfloat16(f[q]);
        hi[q] = h;
        lo[q] = __float2bfloat16(f[q] - __bfloat162float(h));
    }
}
__device__ void prep(const float* __restrict__ Wi, const float* __restrict__ Wh,
                     const float* __restrict__ inputs) {
    const long gtid = (long)blockIdx.x * NTH + threadIdx.x;
    const long gstr = (long)GRID * NTH;
    const long QW = (long)HD * N3H / 4;
    for (long i = gtid; i < 2 * QW; i += gstr) {
        int mat = i >= QW;
        long il = i - (long)mat * QW;
        float4 v = ((const float4*)(mat ? Wh : Wi))[il];
        size_t o = (size_t)mat * HD * N3H + (size_t)il * 4;
        __nv_bfloat16 h4[4], l4[4];
        split4(v, h4, l4);
        *(uint2*)(g_whi + o) = *(uint2*)h4;
        *(uint2*)(g_wlo + o) = *(uint2*)l4;
    }
    const long QX = (long)TS * HD / 4;
    for (long i = gtid; i < QX; i += gstr) {
        float4 v = ((const float4*)inputs)[i];
        size_t o = (size_t)i * 4;
        __nv_bfloat16 h4[4], l4[4];
        split4(v, h4, l4);
        *(uint2*)(g_xhi + o) = *(uint2*)h4;
        *(uint2*)(g_xlo + o) = *(uint2*)l4;
    }
}

// ---------------- staging (cp.async, 256 thr; A 128x32, B 32x256) ----------------
__device__ __forceinline__ void stage(uint32_t smb, int buf, int phase2, int abase,
                                      int rows, int nbase, int kglob,
                                      const __nv_bfloat16* __restrict__ Ahi,
                                      const __nv_bfloat16* __restrict__ Alo,
                                      int mat) {
    const int tid = threadIdx.x;
    const uint32_t bb = smb + buf * BUFSZ;
#pragma unroll
    for (int i = 0; i < 2; i++) {
        int idx = tid + i * NTH;
        int ar = idx >> 2, au = idx & 3;          // 128 rows x 4 slots of 16B
        bool pa = ar < rows;
        size_t so = 0;
        if (pa) {
            int srow = phase2 ? (s_perm[ar] - 1) : (abase + ar);
            so = (size_t)srow * HD + kglob + au * 8;
        }
        cp16(bb + ar * APITCH + au * 16, Ahi + so, pa);
        cp16(bb + SA_PL + ar * APITCH + au * 16, Alo + so, pa);
    }
#pragma unroll
    for (int i = 0; i < 4; i++) {
        int idx = tid + i * NTH;
        int bk = idx >> 5, bu = idx & 31;         // 32 k-rows x 32 slots of 16B
        size_t bo = (size_t)mat * HD * N3H + (size_t)(kglob + bk) * N3H + nbase + bu * 8;
        cp16(bb + 2 * SA_PL + bk * BPITCH + bu * 16, g_whi + bo, true);
        cp16(bb + 2 * SA_PL + SB_PL + bk * BPITCH + bu * 16, g_wlo + bo, true);
    }
}

// ---------------- GEMM tile 128x256, warp tile 64x64 (8 warps, 2x4) ------------
__device__ void mma_tile(int phase2, int permbase, int abase, int rows, int nbase,
                         int k0, int nk,
                         const __nv_bfloat16* __restrict__ Ahi,
                         const __nv_bfloat16* __restrict__ Alo,
                         int mat, const float* __restrict__ bi,
                         float* __restrict__ Cout, int rb,
                         uint32_t smb) {
    const int tid = threadIdx.x;
    const int lane = tid & 31, wid = tid >> 5;
    const int wm = wid & 1, wn = wid >> 1;        // 2 x 4 warp grid

    __syncthreads();
    if (phase2 && tid < 128)
        s_perm[tid] = (tid < rows) ? __ldcg(&g_perm[permbase + tid]) : 1;
    __syncthreads();

    float c[4][8][4];
#pragma unroll
    for (int i = 0; i < 4; i++)
#pragma unroll
        for (int j = 0; j < 8; j++)
#pragma unroll
            for (int q = 0; q < 4; q++) c[i][j][q] = 0.f;

    stage(smb, 0, phase2, abase, rows, nbase, k0, Ahi, Alo, mat);
    cp_commit();

    for (int kb = 0; kb < nk; kb++) {
        const int cur = kb & 1;
        if (kb + 1 < nk) {
            stage(smb, cur ^ 1, phase2, abase, rows, nbase, k0 + (kb + 1) * 32,
                  Ahi, Alo, mat);
            cp_commit();
            cp_wait1();
        } else {
            cp_wait0();
        }
        __syncthreads();

        const uint32_t sa = smb + cur * BUFSZ;
        const uint32_t sb = sa + 2 * SA_PL;
#pragma unroll
        for (int term = 0; term < 3; term++) {
            const uint32_t ab = sa + ((term == 2) ? SA_PL : 0);
            const uint32_t bb = sb + ((term == 1) ? SB_PL : 0);
#pragma unroll
            for (int ks = 0; ks < 2; ks++) {
                uint32_t a[4][4], b[4][4];
#pragma unroll
                for (int mf = 0; mf < 4; mf++)
                    ldm_x4(a[mf], ab + (wm * 64 + mf * 16 + (lane & 15)) * APITCH
                                     + ks * 32 + (lane >> 4) * 16);
#pragma unroll
                for (int p = 0; p < 4; p++)
                    ldm_x4t(b[p], bb + (ks * 16 + (lane & 15)) * BPITCH
                                     + (wn * 64 + p * 16) * 2 + (lane >> 4) * 16);
#pragma unroll
                for (int mf = 0; mf < 4; mf++)
#pragma unroll
                    for (int nf = 0; nf < 8; nf++)
                        mma16816(c[mf][nf], a[mf], &b[nf >> 1][(nf & 1) * 2]);
            }
        }
        __syncthreads();
    }

#pragma unroll
    for (int mf = 0; mf < 4; mf++) {
#pragma unroll
        for (int nf = 0; nf < 8; nf++) {
            int row0 = wm * 64 + mf * 16 + (lane >> 2);
            int col = nbase + wn * 64 + nf * 8 + (lane & 3) * 2;
            float2 v0 = make_float2(c[mf][nf][0], c[mf][nf][1]);
            float2 v1 = make_float2(c[mf][nf][2], c[mf][nf][3]);
            if (bi) {
                float2 bv = *(const float2*)(bi + col);
                v0.x += bv.x; v0.y += bv.y; v1.x += bv.x; v1.y += bv.y;
            }
            if (row0 < rows)
                *(float2*)(Cout + (size_t)(rb + row0) * N3H + col) = v0;
            if (row0 + 8 < rows)
                *(float2*)(Cout + (size_t)(rb + row0 + 8) * N3H + col) = v1;
        }
    }
}

// ---------------- gates ----------------
__device__ __forceinline__ void store_h(float h, int t, int j, float* out) {
    out[(size_t)t * HD + j] = h;
    out[(size_t)(TS + t) * HD + j] = h;
    __nv_bfloat16 hh = __float2bfloat16(h);
    g_hhi[(size_t)t * HD + j] = hh;
    g_hlo[(size_t)t * HD + j] = __float2bfloat16(h - __bfloat162float(hh));
}

__device__ void gates_s0(const float* __restrict__ last_state,
                         const float* __restrict__ Wh,
                         const float* __restrict__ bhn,
                         const int* __restrict__ term,
                         float* __restrict__ out) {
    const int cnt = __ldcg(&g_off[1]);
    const bool term0 = (term[0] != 0);
    const long total = (long)cnt * HD;
    for (long idx = (long)blockIdx.x * NTH + threadIdx.x; idx < total;
         idx += (long)GRID * NTH) {
        int r = (int)(idx >> 10), j = (int)(idx & 1023);
        int t = __ldcg(&g_perm[r]);
        size_t gb = (size_t)t * N3H;
        float gi_r = __ldcg(&g_gi[gb + j]);
        float gi_z = __ldcg(&g_gi[gb + 1024 + j]);
        float gi_n = __ldcg(&g_gi[gb + 2048 + j]);
        float gh_r = 0.f, gh_z = 0.f, gh_n = 0.f, hold = 0.f;
        if (t == 0 && !term0) {
            for (int k = 0; k < HD; k++) {
                float hv = last_state[k];
                const float* wr = Wh + (size_t)k * N3H + j;
                gh_r += hv * wr[0];
                gh_z += hv * wr[1024];
                gh_n += hv * wr[2048];
            }
            hold = last_state[j];
        }
        float rg = 1.f / (1.f + expf(-(gi_r + gh_r)));
        float zg = 1.f / (1.f + expf(-(gi_z + gh_z)));
        float ng = tanhf(gi_n + rg * (gh_n + __ldg(&bhn[j])));
        store_h((1.f - zg) * ng + zg * hold, t, j, out);
    }
}

__device__ void gates_step(int off, int cnt, int KS, const float* __restrict__ bhn,
                           float* __restrict__ out) {
    const long total = (long)cnt * HD;
    for (long idx = (long)blockIdx.x * NTH + threadIdx.x; idx < total;
         idx += (long)GRID * NTH) {
        int r = (int)(idx >> 10), j = (int)(idx & 1023);
        int t = __ldcg(&g_perm[off + r]);
        float ghr, ghz, ghn;
        if (KS == 1) {
            size_t hb = (size_t)(off + r) * N3H;
            ghr = __ldcg(&g_gh[hb + j]);
            ghz = __ldcg(&g_gh[hb + 1024 + j]);
            ghn = __ldcg(&g_gh[hb + 2048 + j]);
        } else {
            ghr = ghz = ghn = 0.f;
            size_t hb = (size_t)r * N3H;
            for (int p = 0; p < KS; p++) {
                const float* pp = g_ghp + (size_t)p * PARTF + hb;
                ghr += __ldcg(&pp[j]);
                ghz += __ldcg(&pp[1024 + j]);
                ghn += __ldcg(&pp[2048 + j]);
            }
        }
        size_t gb = (size_t)t * N3H;
        float gr = __ldcg(&g_gi[gb + j]) + ghr;
        float gz = __ldcg(&g_gi[gb + 1024 + j]) + ghz;
        float gni = __ldcg(&g_gi[gb + 2048 + j]);
        float hold = __ldcg(&out[(size_t)(t - 1) * HD + j]);
        float rg = 1.f / (1.f + expf(-gr));
        float zg = 1.f / (1.f + expf(-gz));
        float ng = tanhf(gni + rg * (ghn + __ldg(&bhn[j])));
        store_h((1.f - zg) * ng + zg * hold, t, j, out);
    }
}

// ---------------- persistent kernel ----------------
__global__ __launch_bounds__(NTH)
void gru_hmma(const float* __restrict__ inputs, const int* __restrict__ term,
              const float* __restrict__ last_state,
              const float* __restrict__ Wi, const float* __restrict__ bi,
              const float* __restrict__ Wh, const float* __restrict__ bhn,
              float* __restrict__ out) {
    extern __shared__ unsigned char smdyn[];
    const uint32_t smb = smem_u32(smdyn);

    if (blockIdx.x == 0) bucketize(term);
    prep(Wi, Wh, inputs);
    grid_sync();

    // phase 1: g_gi = inputs @ Wi + bi  (64 m-tiles x 12 n-tiles of 256)
    for (int tile = blockIdx.x; tile < 64 * 12; tile += GRID) {
        int mt = tile / 12, nt = tile - mt * 12;
        mma_tile(0, 0, mt * 128, 128, nt * 256, 0, 32,
                 g_xhi, g_xlo, 0, bi, g_gi, mt * 128, smb);
    }
    grid_sync();

    gates_s0(last_state, Wh, bhn, term, out);
    grid_sync();

    const int maxL = __ldcg(&g_maxL);
    for (int s = 1; s <= maxL; s++) {
        int off = __ldcg(&g_off[s]);
        int cnt = __ldcg(&g_off[s + 1]) - off;
        int mtn = (cnt + 127) >> 7;
        int KS = pick_ks(mtn);
        int kdep = HD / KS;
        int nkk = kdep / 32;
        int ntile = mtn * 12 * KS;
        for (int tile = blockIdx.x; tile < ntile; tile += GRID) {
            int kt = tile % KS;
            int q = tile / KS;
            int nt = q % 12, mt = q / 12;
            int m0 = mt * 128;
            int rows = min(cnt - m0, 128);
            if (KS == 1) {
                mma_tile(1, off + m0, 0, rows, nt * 256, 0, 32,
                         g_hhi, g_hlo, 1, nullptr, g_gh, off + m0, smb);
            } else {
                mma_tile(1, off + m0, 0, rows, nt * 256, kt * kdep, nkk,
                         g_hhi, g_hlo, 1, nullptr,
                         g_ghp + (size_t)kt * PARTF, m0, smb);
            }
        }
        grid_sync();
        gates_step(off, cnt, KS, bhn, out);
        grid_sync();
    }
}

extern "C" void kernel_launch(void* const* d_in, const int* in_sizes, int n_in,
                              void* d_out, int out_size) {
    const float* inputs     = (const float*)d_in[0];
    const int*   term       = (const int*)d_in[1];
    const float* last_state = (const float*)d_in[2];
    const float* Wi         = (const float*)d_in[3];
    const float* bi         = (const float*)d_in[4];
    const float* Wh         = (const float*)d_in[5];
    const float* bhn        = (const float*)d_in[6];
    float*       out        = (float*)d_out;

    cudaFuncSetAttribute(gru_hmma, cudaFuncAttributeMaxDynamicSharedMemorySize,
                         SMEM_DYN);
    gru_hmma<<<GRID, NTH, SMEM_DYN>>>(inputs, term, last_state, Wi, bi, Wh, bhn, out);
}

// round 14
// speedup vs baseline: 1.3050x; 1.3050x over previous
#include <cuda_runtime.h>
#include <cuda_bf16.h>
#include <stdint.h>

// GRU reset-on-terminate, T=8192, H=1024. Segment-parallel; mma.sync bf16
// with fp32 hi/lo split (3 terms). R13: R12's 3-stage single-sync ring with
// the smem budget actually fitting 2 CTAs/SM (B tiles XOR-swizzled to 256B
// rows, s_perm in dynamic smem; 228.3KB/SM < 233.5KB limit).

#define TS   8192
#define HD   1024
#define N3H  3072
#define NTH  256
#define GRID 296

#define APITCH 80
#define SA_PL  10240                   // 128 rows x 80B
#define SB_PL  8192                    // 32 rows x 256B (XOR swizzle)
#define A_LO_O 10240
#define B_HI_O 20480
#define B_LO_O 28672
#define BUFSZ  36864                   // 2*SA_PL + 2*SB_PL
#define BUF0   512                     // after s_perm
#define SMEM_DYN (BUF0 + 3*BUFSZ)      // 111104; x2 CTAs + static fits 228KB

#define PARTROWS 1536
#define PARTF  ((size_t)PARTROWS*N3H)

__device__ float g_gi[(size_t)TS*N3H];
__device__ float g_gh[(size_t)TS*N3H];
__device__ float g_ghp[(size_t)16*PARTF];
__device__ __nv_bfloat16 g_whi[(size_t)2*HD*N3H];
__device__ __nv_bfloat16 g_wlo[(size_t)2*HD*N3H];
__device__ __nv_bfloat16 g_xhi[(size_t)TS*HD];
__device__ __nv_bfloat16 g_xlo[(size_t)TS*HD];
__device__ __nv_bfloat16 g_hhi[(size_t)TS*HD];
__device__ __nv_bfloat16 g_hlo[(size_t)TS*HD];
__device__ int g_perm[TS], g_cnt[TS], g_off[TS+1], g_l[TS];
__device__ int g_maxL;
__device__ unsigned long long g_bar;

// ---------------- helpers ----------------
__device__ __forceinline__ uint32_t smem_u32(const void* p) {
    uint32_t a;
    asm("{ .reg .u64 t; cvta.to.shared.u64 t, %1; cvt.u32.u64 %0, t; }" : "=r"(a) : "l"(p));
    return a;
}
__device__ __forceinline__ void cp16(uint32_t dst, const void* src, bool pred) {
    int sz = pred ? 16 : 0;
    asm volatile("cp.async.cg.shared.global [%0], [%1], 16, %2;"
                 :: "r"(dst), "l"(src), "r"(sz) : "memory");
}
__device__ __forceinline__ void cp_commit() {
    asm volatile("cp.async.commit_group;" ::: "memory");
}
__device__ __forceinline__ void cp_wait1() {
    asm volatile("cp.async.wait_group 1;" ::: "memory");
}
__device__ __forceinline__ void cp_wait0() {
    asm volatile("cp.async.wait_group 0;" ::: "memory");
}
__device__ __forceinline__ void ldm_x4(uint32_t* r, uint32_t a) {
    asm volatile("ldmatrix.sync.aligned.m8n8.x4.shared.b16 {%0,%1,%2,%3}, [%4];"
        : "=r"(r[0]), "=r"(r[1]), "=r"(r[2]), "=r"(r[3]) : "r"(a));
}
__device__ __forceinline__ void ldm_x4t(uint32_t* r, uint32_t a) {
    asm volatile("ldmatrix.sync.aligned.m8n8.x4.trans.shared.b16 {%0,%1,%2,%3}, [%4];"
        : "=r"(r[0]), "=r"(r[1]), "=r"(r[2]), "=r"(r[3]) : "r"(a));
}
__device__ __forceinline__ void mma16816(float* c, const uint32_t* a, const uint32_t* b) {
    asm volatile("mma.sync.aligned.m16n8k16.row.col.f32.bf16.bf16.f32 "
        "{%0,%1,%2,%3}, {%4,%5,%6,%7}, {%8,%9}, {%0,%1,%2,%3};"
        : "+f"(c[0]), "+f"(c[1]), "+f"(c[2]), "+f"(c[3])
        : "r"(a[0]), "r"(a[1]), "r"(a[2]), "r"(a[3]), "r"(b[0]), "r"(b[1]));
}
__device__ __forceinline__ void grid_sync() {
    __threadfence();
    __syncthreads();
    if (threadIdx.x == 0) {
        unsigned long long my = atomicAdd(&g_bar, 1ULL) + 1ULL;
        unsigned long long target = ((my + GRID - 1ULL) / GRID) * GRID;
        while (atomicAdd(&g_bar, 0ULL) < target) { __nanosleep(128); }
        __threadfence();
    }
    __syncthreads();
}
__device__ __forceinline__ int pick_ks(int mtn) {
    return mtn >= 13 ? 1 : (mtn >= 7 ? 2 : (mtn >= 4 ? 4 : (mtn >= 2 ? 8 : 16)));
}

// ---------------- bucketize (block 0, 256 thr x 32) ----------------
__device__ void bucketize(const int* __restrict__ term) {
    __shared__ int s_cm[NTH], s_ml[NTH];
    const int tid = threadIdx.x;
    for (int i = tid; i < TS; i += NTH) g_cnt[i] = 0;
    __syncthreads();
    const int t0 = tid * 32;
    int cm = -1;
#pragma unroll
    for (int i = 0; i < 32; i++) if (term[t0 + i] != 0) cm = t0 + i;
    s_cm[tid] = cm;
    __syncthreads();
    int pre = -1;
    for (int c = 0; c < tid; c++) pre = max(pre, s_cm[c]);
    int run = pre, ml = 0;
    for (int i = 0; i < 32; i++) {
        int t = t0 + i;
        if (term[t] != 0) run = t;
        int l = (run < 0) ? t : (t - run);
        g_l[t] = l;
        atomicAdd(&g_cnt[l], 1);
        ml = max(ml, l);
    }
    s_ml[tid] = ml;
    __syncthreads();
    if (tid == 0) {
        int m = 0;
        for (int c = 0; c < NTH; c++) m = max(m, s_ml[c]);
        g_maxL = m;
        int o = 0;
        for (int s = 0; s <= m; s++) { g_off[s] = o; o += g_cnt[s]; }
        g_off[m + 1] = o;
        for (int s = 0; s <= m; s++) g_cnt[s] = 0;
    }
    __syncthreads();
    for (int i = 0; i < 32; i++) {
        int t = t0 + i;
        int l = g_l[t];
        int pos = g_off[l] + atomicAdd(&g_cnt[l], 1);
        g_perm[pos] = t;
    }
}

// ---------------- split precompute ----------------
__device__ __forceinline__ void split4(float4 v, __nv_bfloat16* hi, __nv_bfloat16* lo) {
    float f[4] = {v.x, v.y, v.z, v.w};
#pragma unroll
    for (int q = 0; q < 4; q++) {
        __nv_bfloat16 h = __float2bfloat16(f[q]);
        hi[q] = h;
        lo[q] = __float2bfloat16(f[q] - __bfloat162float(h));
    }
}
__device__ void prep(const float* __restrict__ Wi, const float* __restrict__ Wh,
                     const float* __restrict__ inputs) {
    const long gtid = (long)blockIdx.x * NTH + threadIdx.x;
    const long gstr = (long)GRID * NTH;
    const long QW = (long)HD * N3H / 4;
    for (long i = gtid; i < 2 * QW; i += gstr) {
        int mat = i >= QW;
        long il = i - (long)mat * QW;
        float4 v = ((const float4*)(mat ? Wh : Wi))[il];
        size_t o = (size_t)mat * HD * N3H + (size_t)il * 4;
        __nv_bfloat16 h4[4], l4[4];
        split4(v, h4, l4);
        *(uint2*)(g_whi + o) = *(uint2*)h4;
        *(uint2*)(g_wlo + o) = *(uint2*)l4;
    }
    const long QX = (long)TS * HD / 4;
    for (long i = gtid; i < QX; i += gstr) {
        float4 v = ((const float4*)inputs)[i];
        size_t o = (size_t)i * 4;
        __nv_bfloat16 h4[4], l4[4];
        split4(v, h4, l4);
        *(uint2*)(g_xhi + o) = *(uint2*)h4;
        *(uint2*)(g_xlo + o) = *(uint2*)l4;
    }
}

// ---------------- staging (cp.async; A padded 80B, B swizzled 256B) ----------
__device__ __forceinline__ void stage(uint32_t smb, int buf, int phase2, int abase,
                                      int rows, int nbase, int kglob,
                                      const __nv_bfloat16* __restrict__ Ahi,
                                      const __nv_bfloat16* __restrict__ Alo,
                                      int mat, const int* sperm) {
    const int tid = threadIdx.x;
    const uint32_t bb = smb + BUF0 + buf * BUFSZ;
#pragma unroll
    for (int i = 0; i < 2; i++) {
        int idx = tid + i * NTH;
        int ar = idx >> 2, au = idx & 3;          // A: 128 rows x 4 slots of 16B
        bool pa = ar < rows;
        size_t so = 0;
        if (pa) {
            int srow = phase2 ? (sperm[ar] - 1) : (abase + ar);
            so = (size_t)srow * HD + kglob + au * 8;
        }
        cp16(bb + ar * APITCH + au * 16, Ahi + so, pa);
        cp16(bb + A_LO_O + ar * APITCH + au * 16, Alo + so, pa);
        int bk = idx >> 4, bu = idx & 15;         // B: 32 k-rows x 16 chunks
        uint32_t bsw = bk * 256 + ((bu ^ (bk & 7)) << 4);
        size_t bo = (size_t)mat * HD * N3H + (size_t)(kglob + bk) * N3H + nbase + bu * 8;
        cp16(bb + B_HI_O + bsw, g_whi + bo, true);
        cp16(bb + B_LO_O + bsw, g_wlo + bo, true);
    }
}

// ---------------- GEMM tile 128x128, warp tile 64x32 (8 warps, 2x4) ----------
__device__ void mma_tile(int phase2, int permbase, int abase, int rows, int nbase,
                         int k0, int nk,
                         const __nv_bfloat16* __restrict__ Ahi,
                         const __nv_bfloat16* __restrict__ Alo,
                         int mat, const float* __restrict__ bi,
                         float* __restrict__ Cout, int rb,
                         uint32_t smb, int* sperm) {
    const int tid = threadIdx.x;
    const int lane = tid & 31, wid = tid >> 5;
    const int wm = wid & 1, wn = wid >> 1;        // 2 x 4 warp grid

    __syncthreads();   // guards sperm overwrite AND ring-buffer restart
    if (phase2 && tid < 128)
        sperm[tid] = (tid < rows) ? __ldcg(&g_perm[permbase + tid]) : 1;
    __syncthreads();

    float c[4][4][4];
#pragma unroll
    for (int i = 0; i < 4; i++)
#pragma unroll
        for (int j = 0; j < 4; j++)
#pragma unroll
            for (int q = 0; q < 4; q++) c[i][j][q] = 0.f;

    stage(smb, 0, phase2, abase, rows, nbase, k0, Ahi, Alo, mat, sperm);
    cp_commit();

    int cur = 0, nxt = 1;
    for (int kb = 0; kb < nk; kb++) {
        if (kb + 1 < nk) {
            // distance-1 prefetch into 3-stage ring: buffer nxt was last read
            // at iteration kb-2; the single sync at kb-1 ordered that read.
            stage(smb, nxt, phase2, abase, rows, nbase, k0 + (kb + 1) * 32,
                  Ahi, Alo, mat, sperm);
            cp_commit();
            cp_wait1();
        } else {
            cp_wait0();
        }
        __syncthreads();   // the ONLY sync per chunk

        const uint32_t sa = smb + BUF0 + cur * BUFSZ;
#pragma unroll
        for (int term = 0; term < 3; term++) {
            const uint32_t ab = sa + ((term == 2) ? A_LO_O : 0);
            const uint32_t bbs = sa + ((term == 1) ? B_LO_O : B_HI_O);
#pragma unroll
            for (int ks = 0; ks < 2; ks++) {
                uint32_t a[4][4], b[2][4];
#pragma unroll
                for (int mf = 0; mf < 4; mf++)
                    ldm_x4(a[mf], ab + (wm * 64 + mf * 16 + (lane & 15)) * APITCH
                                     + ks * 32 + (lane >> 4) * 16);
#pragma unroll
                for (int p = 0; p < 2; p++) {
                    int row = ks * 16 + (lane & 15);
                    int ch  = wn * 4 + p * 2 + (lane >> 4);
                    ldm_x4t(b[p], bbs + row * 256 + ((ch ^ (row & 7)) << 4));
                }
#pragma unroll
                for (int mf = 0; mf < 4; mf++)
#pragma unroll
                    for (int nf = 0; nf < 4; nf++)
                        mma16816(c[mf][nf], a[mf], &b[nf >> 1][(nf & 1) * 2]);
            }
        }
        cur = nxt;
        nxt = (nxt == 2) ? 0 : nxt + 1;
    }

#pragma unroll
    for (int mf = 0; mf < 4; mf++) {
#pragma unroll
        for (int nf = 0; nf < 4; nf++) {
            int row0 = wm * 64 + mf * 16 + (lane >> 2);
            int col = nbase + wn * 32 + nf * 8 + (lane & 3) * 2;
            float2 v0 = make_float2(c[mf][nf][0], c[mf][nf][1]);
            float2 v1 = make_float2(c[mf][nf][2], c[mf][nf][3]);
            if (bi) {
                float2 bv = *(const float2*)(bi + col);
                v0.x += bv.x; v0.y += bv.y; v1.x += bv.x; v1.y += bv.y;
            }
            if (row0 < rows)
                *(float2*)(Cout + (size_t)(rb + row0) * N3H + col) = v0;
            if (row0 + 8 < rows)
                *(float2*)(Cout + (size_t)(rb + row0 + 8) * N3H + col) = v1;
        }
    }
}

// ---------------- gates ----------------
__device__ __forceinline__ void store_h(float h, int t, int j, float* out) {
    out[(size_t)t * HD + j] = h;
    out[(size_t)(TS + t) * HD + j] = h;
    __nv_bfloat16 hh = __float2bfloat16(h);
    g_hhi[(size_t)t * HD + j] = hh;
    g_hlo[(size_t)t * HD + j] = __float2bfloat16(h - __bfloat162float(hh));
}

__device__ void gates_s0(const float* __restrict__ last_state,
                         const float* __restrict__ Wh,
                         const float* __restrict__ bhn,
                         const int* __restrict__ term,
                         float* __restrict__ out) {
    const int cnt = __ldcg(&g_off[1]);
    const bool term0 = (term[0] != 0);
    const long total = (long)cnt * HD;
    for (long idx = (long)blockIdx.x * NTH + threadIdx.x; idx < total;
         idx += (long)GRID * NTH) {
        int r = (int)(idx >> 10), j = (int)(idx & 1023);
        int t = __ldcg(&g_perm[r]);
        size_t gb = (size_t)t * N3H;
        float gi_r = __ldcg(&g_gi[gb + j]);
        float gi_z = __ldcg(&g_gi[gb + 1024 + j]);
        float gi_n = __ldcg(&g_gi[gb + 2048 + j]);
        float gh_r = 0.f, gh_z = 0.f, gh_n = 0.f, hold = 0.f;
        if (t == 0 && !term0) {
            for (int k = 0; k < HD; k++) {
                float hv = last_state[k];
                const float* wr = Wh + (size_t)k * N3H + j;
                gh_r += hv * wr[0];
                gh_z += hv * wr[1024];
                gh_n += hv * wr[2048];
            }
            hold = last_state[j];
        }
        float rg = 1.f / (1.f + expf(-(gi_r + gh_r)));
        float zg = 1.f / (1.f + expf(-(gi_z + gh_z)));
        float ng = tanhf(gi_n + rg * (gh_n + __ldg(&bhn[j])));
        store_h((1.f - zg) * ng + zg * hold, t, j, out);
    }
}

__device__ void gates_step(int off, int cnt, int KS, const float* __restrict__ bhn,
                           float* __restrict__ out) {
    const long total = (long)cnt * HD;
    for (long idx = (long)blockIdx.x * NTH + threadIdx.x; idx < total;
         idx += (long)GRID * NTH) {
        int r = (int)(idx >> 10), j = (int)(idx & 1023);
        int t = __ldcg(&g_perm[off + r]);
        float ghr, ghz, ghn;
        if (KS == 1) {
            size_t hb = (size_t)(off + r) * N3H;
            ghr = __ldcg(&g_gh[hb + j]);
            ghz = __ldcg(&g_gh[hb + 1024 + j]);
            ghn = __ldcg(&g_gh[hb + 2048 + j]);
        } else {
            ghr = ghz = ghn = 0.f;
            size_t hb = (size_t)r * N3H;
            for (int p = 0; p < KS; p++) {
                const float* pp = g_ghp + (size_t)p * PARTF + hb;
                ghr += __ldcg(&pp[j]);
                ghz += __ldcg(&pp[1024 + j]);
                ghn += __ldcg(&pp[2048 + j]);
            }
        }
        size_t gb = (size_t)t * N3H;
        float gr = __ldcg(&g_gi[gb + j]) + ghr;
        float gz = __ldcg(&g_gi[gb + 1024 + j]) + ghz;
        float gni = __ldcg(&g_gi[gb + 2048 + j]);
        float hold = __ldcg(&out[(size_t)(t - 1) * HD + j]);
        float rg = 1.f / (1.f + expf(-gr));
        float zg = 1.f / (1.f + expf(-gz));
        float ng = tanhf(gni + rg * (ghn + __ldg(&bhn[j])));
        store_h((1.f - zg) * ng + zg * hold, t, j, out);
    }
}

// ---------------- persistent kernel ----------------
__global__ __launch_bounds__(NTH, 2)
void gru_hmma(const float* __restrict__ inputs, const int* __restrict__ term,
              const float* __restrict__ last_state,
              const float* __restrict__ Wi, const float* __restrict__ bi,
              const float* __restrict__ Wh, const float* __restrict__ bhn,
              float* __restrict__ out) {
    extern __shared__ unsigned char smdyn[];
    const uint32_t smb = smem_u32(smdyn);
    int* sperm = (int*)smdyn;

    if (blockIdx.x == 0) bucketize(term);
    prep(Wi, Wh, inputs);
    grid_sync();

    // phase 1: g_gi = inputs @ Wi + bi  (64 m-tiles x 24 n-tiles)
    for (int tile = blockIdx.x; tile < 64 * 24; tile += GRID) {
        int mt = tile / 24, nt = tile - mt * 24;
        mma_tile(0, 0, mt * 128, 128, nt * 128, 0, 32,
                 g_xhi, g_xlo, 0, bi, g_gi, mt * 128, smb, sperm);
    }
    grid_sync();

    gates_s0(last_state, Wh, bhn, term, out);
    grid_sync();

    const int maxL = __ldcg(&g_maxL);
    for (int s = 1; s <= maxL; s++) {
        int off = __ldcg(&g_off[s]);
        int cnt = __ldcg(&g_off[s + 1]) - off;
        int mtn = (cnt + 127) >> 7;
        int KS = pick_ks(mtn);
        int kdep = HD / KS;
        int nkk = kdep / 32;
        int ntile = mtn * 24 * KS;
        for (int tile = blockIdx.x; tile < ntile; tile += GRID) {
            int kt = tile % KS;
            int q = tile / KS;
            int nt = q % 24, mt = q / 24;
            int m0 = mt * 128;
            int rows = min(cnt - m0, 128);
            if (KS == 1) {
                mma_tile(1, off + m0, 0, rows, nt * 128, 0, 32,
                         g_hhi, g_hlo, 1, nullptr, g_gh, off + m0, smb, sperm);
            } else {
                mma_tile(1, off + m0, 0, rows, nt * 128, kt * kdep, nkk,
                         g_hhi, g_hlo, 1, nullptr,
                         g_ghp + (size_t)kt * PARTF, m0, smb, sperm);
            }
        }
        grid_sync();
        gates_step(off, cnt, KS, bhn, out);
        grid_sync();
    }
}

extern "C" void kernel_launch(void* const* d_in, const int* in_sizes, int n_in,
                              void* d_out, int out_size) {
    const float* inputs     = (const float*)d_in[0];
    const int*   term       = (const int*)d_in[1];
    const float* last_state = (const float*)d_in[2];
    const float* Wi         = (const float*)d_in[3];
    const float* bi         = (const float*)d_in[4];
    const float* Wh         = (const float*)d_in[5];
    const float* bhn        = (const float*)d_in[6];
    float*       out        = (float*)d_out;

    cudaFuncSetAttribute(gru_hmma, cudaFuncAttributeMaxDynamicSharedMemorySize,
                         SMEM_DYN);
    gru_hmma<<<GRID, NTH, SMEM_DYN>>>(inputs, term, last_state, Wi, bi, Wh, bhn, out);
}